// round 9
// baseline (speedup 1.0000x reference)
#include <cuda_runtime.h>

// ---------------------------------------------------------------------------
// Leaky CTRNN persistent scan, v5. B=64, T=512, D_IN=256, H=1024, D_OUT=256
//
//  k2: rnn_persistent — 147 blocks x 512 thr (1/SM, co-resident), 514 phases:
//       role r = bid/49 in {0,1,2}; block j = bid%49 owns cols
//       [(1024 j)/49, (1024(j+1))/49)  (20-21 cols, padded to 24 in smem).
//       role0: fr0(p)   = relu(v0=.9v0+.1(fr0(p-1)@Wrec0^T + xin0))
//       role1: pin(p-1) = fr0(p-1)@Win1^T + b1
//       role2: fr1(p-2) = relu(v1=.9v1+.1(fr1(p-3)@Wrec1^T + pin))
//      Weights persist in smem (zero-padded). A staged per 128-k chunk via
//      cp.async.bulk + mbarrier, double-buffered. Split-K x8, microtile
//      8 batches x 3 cols, packed fma.rn.f32x2 ordered for .reuse.
//      Strided d_out stores deferred past barrier arrival.
// ---------------------------------------------------------------------------

namespace {
constexpr int B = 64, T = 512, DIN = 256, H = 1024, DOUT = 256;
constexpr float AL = 0.1f, OMA = 0.9f;

constexpr int NBR   = 49;            // blocks per role
constexpr int NBLK  = 3 * NBR;       // 147
constexpr int THR   = 512;
constexpr int NCOLP = 24;            // padded col count per block
constexpr int KC    = 128;           // k-chunk staged in smem
constexpr int NCH   = H / KC;        // 8
constexpr int HB    = H * B;
constexpr int ABUF  = 2 * KC * B;    // floats (64KB), reused for reduce
constexpr int CBYTES = KC * B * 4;   // 32768
constexpr int MBAR_OFF = (ABUF + H * NCOLP) * 4;   // 64KB + 96KB
constexpr int SMEM_P   = MBAR_OFF + 16;
}

// Scratch (__device__ globals: allocation-free rule)
__device__ float g_xin0[(size_t)T * H * B];   // [t][h][b]
__device__ float g_s0f[(size_t)T * H * B];    // fr0 history [t][h][b]
__device__ float g_s1f[(size_t)T * H * B];    // fr1 history [t][h][b]
__device__ float g_pin[2 * (size_t)H * B];    // [t&1][h][b]
__device__ volatile unsigned g_gen;
__device__ unsigned g_cnt;

// ---- helpers ---------------------------------------------------------------
__device__ __forceinline__ unsigned long long dup2(float x) {
    unsigned long long d;
    asm("mov.b64 %0, {%1, %1};" : "=l"(d) : "r"(__float_as_uint(x)));
    return d;
}
__device__ __forceinline__ void fma2(unsigned long long& a,
                                     unsigned long long x, unsigned long long y) {
    asm("fma.rn.f32x2 %0, %1, %2, %0;" : "+l"(a) : "l"(x), "l"(y));
}
__device__ __forceinline__ void mbar_init(unsigned mbar, unsigned count) {
    asm volatile("mbarrier.init.shared.b64 [%0], %1;" :: "r"(mbar), "r"(count)
                 : "memory");
}
__device__ __forceinline__ void mbar_expect_tx(unsigned mbar, unsigned bytes) {
    asm volatile("mbarrier.arrive.expect_tx.shared.b64 _, [%0], %1;"
                 :: "r"(mbar), "r"(bytes) : "memory");
}
__device__ __forceinline__ void bulk_g2s(unsigned dst, const float* src,
                                         unsigned bytes, unsigned mbar) {
    asm volatile(
        "cp.async.bulk.shared::cta.global.mbarrier::complete_tx::bytes "
        "[%0], [%1], %2, [%3];"
        :: "r"(dst), "l"(src), "r"(bytes), "r"(mbar) : "memory");
}
__device__ __forceinline__ void mbar_wait(unsigned mbar, unsigned parity) {
    asm volatile(
        "{\n\t"
        ".reg .pred P;\n\t"
        "LAB_%=:\n\t"
        "mbarrier.try_wait.parity.shared.b64 P, [%0], %1;\n\t"
        "@!P bra LAB_%=;\n\t"
        "}\n"
        :: "r"(mbar), "r"(parity) : "memory");
}

// ---------------------------------------------------------------------------
__global__ void __launch_bounds__(THR, 1)
rnn_persistent(const float* __restrict__ Wrec0, const float* __restrict__ Win1,
               const float* __restrict__ Wrec1, const float* __restrict__ b1,
               float* __restrict__ states0, float* __restrict__ states1)
{
    extern __shared__ float sm[];
    float* aS = sm;                  // [2][KC][B], reused as reduce scratch
    float* wS = sm + ABUF;           // [H][NCOLP] k-major, zero-padded

    const unsigned sbase = (unsigned)__cvta_generic_to_shared(sm);
    const unsigned mb0 = sbase + MBAR_OFF;
    const unsigned mb1 = sbase + MBAR_OFF + 8;
    const unsigned abuf0 = sbase;
    const unsigned abuf1 = sbase + CBYTES;

    const int tid  = threadIdx.x;
    const int role = (int)blockIdx.x / NBR;
    const int j    = (int)blockIdx.x - role * NBR;
    const int n0   = (j * H) / NBR;
    const int n1   = ((j + 1) * H) / NBR;
    const int ncol = n1 - n0;            // 20 or 21

    // split-K slice / microtile mapping
    const int kt     = tid >> 6;         // k-slice 0..7
    const int tl     = tid & 63;
    const int bgroup = tl & 7;           // 8 batches -> bbase = bgroup*8
    const int cgroup = tl >> 3;          // 3 cols    -> cbase = cgroup*3
    const int bbase  = bgroup * 8;
    const int cbase  = cgroup * 3;

    // One-time weight load: wS[k][n] = W[n0+n][k], zero for n >= ncol
    const float* Wsrc = role == 0 ? Wrec0 : (role == 1 ? Win1 : Wrec1);
    for (int it = tid; it < NCOLP * (H / 4); it += THR) {
        int n  = it % NCOLP;
        int k4 = (it / NCOLP) * 4;
        float4 w = make_float4(0.f, 0.f, 0.f, 0.f);
        if (n < ncol) w = *(const float4*)(Wsrc + (size_t)(n0 + n) * H + k4);
        wS[(k4 + 0) * NCOLP + n] = w.x; wS[(k4 + 1) * NCOLP + n] = w.y;
        wS[(k4 + 2) * NCOLP + n] = w.z; wS[(k4 + 3) * NCOLP + n] = w.w;
    }
    // epilogue mapping: 4 contiguous batches of one col per thread
    const int en = tid >> 4;             // local col 0..31 (active if < ncol)
    const int eb = (tid & 15) * 4;       // batch base 0..60
    const bool ecol = (en < ncol);
    const float b1v = (role == 1 && ecol) ? b1[n0 + en] : 0.f;

    if (tid == 0) { mbar_init(mb0, 1); mbar_init(mb1, 1); }
    asm volatile("fence.proxy.async.shared::cta;" ::: "memory");
    __syncthreads();

    unsigned par0 = 0, par1 = 0;
    float v[4] = {0.f, 0.f, 0.f, 0.f};

    for (int p = 0; p < T + 2; p++) {
        int t; const float* asrc = nullptr; bool act, dogemm;
        if (role == 0) {
            t = p; act = (t < T); dogemm = act && (p > 0);
            if (dogemm) asrc = g_s0f + (size_t)(p - 1) * HB;
        } else if (role == 1) {
            t = p - 1; act = (t >= 0 && t < T); dogemm = act;
            if (dogemm) asrc = g_s0f + (size_t)t * HB;
        } else {
            t = p - 2; act = (t >= 0 && t < T); dogemm = act && (t > 0);
            if (dogemm) asrc = g_s1f + (size_t)(t - 1) * HB;
        }

        // acc[col 0..2][batch-pair 0..3]
        unsigned long long acc[3][4];
        #pragma unroll
        for (int c2 = 0; c2 < 3; c2++)
            #pragma unroll
            for (int q = 0; q < 4; q++) acc[c2][q] = 0ull;

        if (dogemm) {
            if (tid == 0) {                       // prefetch chunk 0
                mbar_expect_tx(mb0, CBYTES);
                bulk_g2s(abuf0, asrc, CBYTES, mb0);
            }
            for (int c = 0; c < NCH; c++) {
                if (c + 1 < NCH && tid == 0) {    // prefetch chunk c+1
                    unsigned dst = ((c + 1) & 1) ? abuf1 : abuf0;
                    unsigned mbn = ((c + 1) & 1) ? mb1 : mb0;
                    mbar_expect_tx(mbn, CBYTES);
                    bulk_g2s(dst, asrc + (size_t)(c + 1) * KC * B, CBYTES, mbn);
                }
                if (c & 1) { mbar_wait(mb1, par1); par1 ^= 1; }
                else       { mbar_wait(mb0, par0); par0 ^= 1; }

                const float* ab = aS + (c & 1) * (KC * B) + (kt * 16) * B + bbase;
                const float* wb = wS + (c * KC + kt * 16) * NCOLP + cbase;
                #pragma unroll
                for (int kk = 0; kk < 16; kk++) {
                    ulonglong2 A0 = *(const ulonglong2*)(ab + kk * B);      // b..b+3
                    ulonglong2 A1 = *(const ulonglong2*)(ab + kk * B + 4);  // b+4..b+7
                    unsigned long long w0 = dup2(wb[kk * NCOLP + 0]);
                    unsigned long long w1 = dup2(wb[kk * NCOLP + 1]);
                    unsigned long long w2 = dup2(wb[kk * NCOLP + 2]);
                    // ordered so consecutive FFMA2 share the A operand (.reuse)
                    fma2(acc[0][0], A0.x, w0); fma2(acc[1][0], A0.x, w1);
                    fma2(acc[2][0], A0.x, w2);
                    fma2(acc[0][1], A0.y, w0); fma2(acc[1][1], A0.y, w1);
                    fma2(acc[2][1], A0.y, w2);
                    fma2(acc[0][2], A1.x, w0); fma2(acc[1][2], A1.x, w1);
                    fma2(acc[2][2], A1.x, w2);
                    fma2(acc[0][3], A1.y, w0); fma2(acc[1][3], A1.y, w1);
                    fma2(acc[2][3], A1.y, w2);
                }
                __syncthreads();   // all reads of this buffer done
            }
        }

        float fr[4];
        bool havefr = false;

        if (act) {
            // split-K partials -> smem: red[n][kt][pair]
            unsigned long long* red = (unsigned long long*)aS;
            #pragma unroll
            for (int c2 = 0; c2 < 3; c2++)
                #pragma unroll
                for (int q = 0; q < 4; q++)
                    red[(cbase + c2) * 256 + kt * 32 + bgroup * 4 + q] = acc[c2][q];
            __syncthreads();

            if (ecol) {
                float4 s = make_float4(0.f, 0.f, 0.f, 0.f);
                #pragma unroll
                for (int q = 0; q < 8; q++) {
                    float4 pz = *(const float4*)&aS[en * 512 + q * 64 + eb];
                    s.x += pz.x; s.y += pz.y; s.z += pz.z; s.w += pz.w;
                }
                const size_t vo = ((size_t)t * H + n0 + en) * B + eb;
                if (role == 1) {
                    float4 o = make_float4(s.x + b1v, s.y + b1v,
                                           s.z + b1v, s.w + b1v);
                    *(float4*)&g_pin[(size_t)(t & 1) * HB +
                                     (size_t)(n0 + en) * B + eb] = o;
                } else {
                    float4 add;
                    if (role == 0)
                        add = *(const float4*)&g_xin0[vo];
                    else
                        add = __ldcg((const float4*)&g_pin[(size_t)(t & 1) * HB +
                                                           (size_t)(n0 + en) * B + eb]);
                    v[0] = OMA * v[0] + AL * (s.x + add.x);
                    v[1] = OMA * v[1] + AL * (s.y + add.y);
                    v[2] = OMA * v[2] + AL * (s.z + add.z);
                    v[3] = OMA * v[3] + AL * (s.w + add.w);
                    fr[0] = fmaxf(v[0], 0.f); fr[1] = fmaxf(v[1], 0.f);
                    fr[2] = fmaxf(v[2], 0.f); fr[3] = fmaxf(v[3], 0.f);
                    havefr = true;
                    float* dst = (role == 0) ? g_s0f : g_s1f;
                    *(float4*)&dst[vo] = make_float4(fr[0], fr[1], fr[2], fr[3]);
                }
            }
        }

        if (p < T + 1) {
            // -- grid barrier, arrival first; strided d_out stores hidden under wait
            __syncthreads();
            unsigned gen;
            if (tid == 0) {
                __threadfence();
                gen = g_gen;
                if (atomicAdd(&g_cnt, 1u) == NBLK - 1) {
                    g_cnt = 0;
                    __threadfence();
                    g_gen = gen + 1;
                }
            }
            if (havefr) {   // d_out states store (not consumed in-kernel)
                float* st = (role == 0) ? states0 : states1;
                #pragma unroll
                for (int bl = 0; bl < 4; bl++)
                    st[((size_t)(eb + bl) * T + t) * H + n0 + en] = fr[bl];
            }
            if (tid == 0) {
                while (g_gen == gen) {}
                __threadfence();
            }
            __syncthreads();
        } else if (havefr) {   // last phase: just store
            float* st = (role == 0) ? states0 : states1;
            #pragma unroll
            for (int bl = 0; bl < 4; bl++)
                st[((size_t)(eb + bl) * T + t) * H + n0 + en] = fr[bl];
        }
    }
}

// ---------------------------------------------------------------------------
// gemm_in0: per timestep t, xin0[t][h][b] = W_in0[h,:] . x[b,t,:] + b0[h]
// ---------------------------------------------------------------------------
__global__ void __launch_bounds__(256)
gemm_in0_kernel(const float* __restrict__ x,
                const float* __restrict__ Win0,
                const float* __restrict__ b0)
{
    __shared__ float aS[16 * 64];
    __shared__ float bS[16 * 64];
    const int tid = threadIdx.x;
    const int m0 = blockIdx.x * 64;
    const int t  = blockIdx.y;
    const int lr = tid >> 2;
    const int lk = (tid & 3) * 4;
    const int tm4 = (tid >> 4) * 4;
    const int tn4 = (tid & 15) * 4;
    float acc[4][4] = {};
    const float* ap = Win0 + (size_t)(m0 + lr) * DIN + lk;
    const float* bp = x + ((size_t)lr * T + t) * DIN + lk;

    for (int k0 = 0; k0 < DIN; k0 += 16) {
        float4 av = *(const float4*)(ap + k0);
        float4 bv = *(const float4*)(bp + k0);
        __syncthreads();
        aS[(lk + 0) * 64 + lr] = av.x; aS[(lk + 1) * 64 + lr] = av.y;
        aS[(lk + 2) * 64 + lr] = av.z; aS[(lk + 3) * 64 + lr] = av.w;
        bS[(lk + 0) * 64 + lr] = bv.x; bS[(lk + 1) * 64 + lr] = bv.y;
        bS[(lk + 2) * 64 + lr] = bv.z; bS[(lk + 3) * 64 + lr] = bv.w;
        __syncthreads();
        #pragma unroll
        for (int kk = 0; kk < 16; kk++) {
            float4 a = *(const float4*)&aS[kk * 64 + tm4];
            float4 b = *(const float4*)&bS[kk * 64 + tn4];
            acc[0][0] += a.x * b.x; acc[0][1] += a.x * b.y;
            acc[0][2] += a.x * b.z; acc[0][3] += a.x * b.w;
            acc[1][0] += a.y * b.x; acc[1][1] += a.y * b.y;
            acc[1][2] += a.y * b.z; acc[1][3] += a.y * b.w;
            acc[2][0] += a.z * b.x; acc[2][1] += a.z * b.y;
            acc[2][2] += a.z * b.z; acc[2][3] += a.z * b.w;
            acc[3][0] += a.w * b.x; acc[3][1] += a.w * b.y;
            acc[3][2] += a.w * b.z; acc[3][3] += a.w * b.w;
        }
    }
    #pragma unroll
    for (int i = 0; i < 4; i++) {
        float bb = b0[m0 + tm4 + i];
        float4 o = make_float4(acc[i][0] + bb, acc[i][1] + bb,
                               acc[i][2] + bb, acc[i][3] + bb);
        *(float4*)&g_xin0[((size_t)t * H + m0 + tm4 + i) * B + tn4] = o;
    }
}

// ---------------------------------------------------------------------------
// gemm_out: output[B*T, DOUT] = states1[B*T, H] @ W_out^T + b_out
// ---------------------------------------------------------------------------
__global__ void __launch_bounds__(256)
gemm_out_kernel(const float* __restrict__ states1,
                const float* __restrict__ Wout,
                const float* __restrict__ bout,
                float* __restrict__ out)
{
    __shared__ float aS[16 * 64];
    __shared__ float bS[16 * 64];
    const int tid = threadIdx.x;
    const int m0 = blockIdx.x * 64;
    const int n0 = blockIdx.y * 64;
    const int lr = tid >> 2;
    const int lk = (tid & 3) * 4;
    const int tm4 = (tid >> 4) * 4;
    const int tn4 = (tid & 15) * 4;
    float acc[4][4] = {};
    const float* ap = states1 + (size_t)(m0 + lr) * H + lk;
    const float* bp = Wout    + (size_t)(n0 + lr) * H + lk;

    for (int k0 = 0; k0 < H; k0 += 16) {
        float4 av = *(const float4*)(ap + k0);
        float4 bv = *(const float4*)(bp + k0);
        __syncthreads();
        aS[(lk + 0) * 64 + lr] = av.x; aS[(lk + 1) * 64 + lr] = av.y;
        aS[(lk + 2) * 64 + lr] = av.z; aS[(lk + 3) * 64 + lr] = av.w;
        bS[(lk + 0) * 64 + lr] = bv.x; bS[(lk + 1) * 64 + lr] = bv.y;
        bS[(lk + 2) * 64 + lr] = bv.z; bS[(lk + 3) * 64 + lr] = bv.w;
        __syncthreads();
        #pragma unroll
        for (int kk = 0; kk < 16; kk++) {
            float4 a = *(const float4*)&aS[kk * 64 + tm4];
            float4 b = *(const float4*)&bS[kk * 64 + tn4];
            acc[0][0] += a.x * b.x; acc[0][1] += a.x * b.y;
            acc[0][2] += a.x * b.z; acc[0][3] += a.x * b.w;
            acc[1][0] += a.y * b.x; acc[1][1] += a.y * b.y;
            acc[1][2] += a.y * b.z; acc[1][3] += a.y * b.w;
            acc[2][0] += a.z * b.x; acc[2][1] += a.z * b.y;
            acc[2][2] += a.z * b.z; acc[2][3] += a.z * b.w;
            acc[3][0] += a.w * b.x; acc[3][1] += a.w * b.y;
            acc[3][2] += a.w * b.z; acc[3][3] += a.w * b.w;
        }
    }
    #pragma unroll
    for (int i = 0; i < 4; i++) {
        float4 bb = *(const float4*)&bout[n0 + tn4];
        int gm = m0 + tm4 + i;
        float4 o = make_float4(acc[i][0] + bb.x, acc[i][1] + bb.y,
                               acc[i][2] + bb.z, acc[i][3] + bb.w);
        *(float4*)&out[(size_t)gm * DOUT + n0 + tn4] = o;
    }
}

// ---------------------------------------------------------------------------
extern "C" void kernel_launch(void* const* d_in, const int* in_sizes, int n_in,
                              void* d_out, int out_size)
{
    (void)in_sizes; (void)n_in; (void)out_size;
    const float* x     = (const float*)d_in[0];
    const float* Win0  = (const float*)d_in[1];
    const float* Wrec0 = (const float*)d_in[2];
    const float* b0    = (const float*)d_in[3];
    const float* Win1  = (const float*)d_in[4];
    const float* Wrec1 = (const float*)d_in[5];
    const float* b1    = (const float*)d_in[6];
    const float* Wout  = (const float*)d_in[7];
    const float* bout  = (const float*)d_in[8];

    float* out     = (float*)d_out;                   // [B][T][DOUT]
    float* states0 = out + (size_t)B * T * DOUT;      // [B][T][H]
    float* states1 = states0 + (size_t)B * T * H;     // [B][T][H]

    cudaFuncSetAttribute(rnn_persistent,
                         cudaFuncAttributeMaxDynamicSharedMemorySize, SMEM_P);

    gemm_in0_kernel<<<dim3(H / 64, T), 256>>>(x, Win0, b0);
    rnn_persistent<<<NBLK, THR, SMEM_P>>>(Wrec0, Win1, Wrec1, b1,
                                          states0, states1);
    gemm_out_kernel<<<dim3((B * T) / 64, DOUT / 64), 256>>>(states1, Wout,
                                                            bout, out);
}

// round 10
// speedup vs baseline: 1.0005x; 1.0005x over previous
#include <cuda_runtime.h>

// ---------------------------------------------------------------------------
// Leaky CTRNN persistent scan, v5. B=64, T=512, D_IN=256, H=1024, D_OUT=256
//
//  k2: rnn_persistent — 147 blocks x 512 thr (1/SM, co-resident), 514 phases:
//       role r = bid/49 in {0,1,2}; block j = bid%49 owns cols
//       [(1024 j)/49, (1024(j+1))/49)  (20-21 cols, padded to 24 in smem).
//       role0: fr0(p)   = relu(v0=.9v0+.1(fr0(p-1)@Wrec0^T + xin0))
//       role1: pin(p-1) = fr0(p-1)@Win1^T + b1
//       role2: fr1(p-2) = relu(v1=.9v1+.1(fr1(p-3)@Wrec1^T + pin))
//      Weights persist in smem (zero-padded). A staged per 128-k chunk via
//      cp.async.bulk + mbarrier, double-buffered. Split-K x8, microtile
//      8 batches x 3 cols, packed fma.rn.f32x2 ordered for .reuse.
//      Strided d_out stores deferred past barrier arrival.
// ---------------------------------------------------------------------------

namespace {
constexpr int B = 64, T = 512, DIN = 256, H = 1024, DOUT = 256;
constexpr float AL = 0.1f, OMA = 0.9f;

constexpr int NBR   = 49;            // blocks per role
constexpr int NBLK  = 3 * NBR;       // 147
constexpr int THR   = 512;
constexpr int NCOLP = 24;            // padded col count per block
constexpr int KC    = 128;           // k-chunk staged in smem
constexpr int NCH   = H / KC;        // 8
constexpr int HB    = H * B;
constexpr int ABUF  = 2 * KC * B;    // floats (64KB), reused for reduce
constexpr int CBYTES = KC * B * 4;   // 32768
constexpr int MBAR_OFF = (ABUF + H * NCOLP) * 4;   // 64KB + 96KB
constexpr int SMEM_P   = MBAR_OFF + 16;
}

// Scratch (__device__ globals: allocation-free rule)
__device__ float g_xin0[(size_t)T * H * B];   // [t][h][b]
__device__ float g_s0f[(size_t)T * H * B];    // fr0 history [t][h][b]
__device__ float g_s1f[(size_t)T * H * B];    // fr1 history [t][h][b]
__device__ float g_pin[2 * (size_t)H * B];    // [t&1][h][b]
__device__ volatile unsigned g_gen;
__device__ unsigned g_cnt;

// ---- helpers ---------------------------------------------------------------
__device__ __forceinline__ unsigned long long dup2(float x) {
    unsigned long long d;
    asm("mov.b64 %0, {%1, %1};" : "=l"(d) : "r"(__float_as_uint(x)));
    return d;
}
__device__ __forceinline__ void fma2(unsigned long long& a,
                                     unsigned long long x, unsigned long long y) {
    asm("fma.rn.f32x2 %0, %1, %2, %0;" : "+l"(a) : "l"(x), "l"(y));
}
__device__ __forceinline__ void mbar_init(unsigned mbar, unsigned count) {
    asm volatile("mbarrier.init.shared.b64 [%0], %1;" :: "r"(mbar), "r"(count)
                 : "memory");
}
__device__ __forceinline__ void mbar_expect_tx(unsigned mbar, unsigned bytes) {
    asm volatile("mbarrier.arrive.expect_tx.shared.b64 _, [%0], %1;"
                 :: "r"(mbar), "r"(bytes) : "memory");
}
__device__ __forceinline__ void bulk_g2s(unsigned dst, const float* src,
                                         unsigned bytes, unsigned mbar) {
    asm volatile(
        "cp.async.bulk.shared::cta.global.mbarrier::complete_tx::bytes "
        "[%0], [%1], %2, [%3];"
        :: "r"(dst), "l"(src), "r"(bytes), "r"(mbar) : "memory");
}
__device__ __forceinline__ void mbar_wait(unsigned mbar, unsigned parity) {
    asm volatile(
        "{\n\t"
        ".reg .pred P;\n\t"
        "LAB_%=:\n\t"
        "mbarrier.try_wait.parity.shared.b64 P, [%0], %1;\n\t"
        "@!P bra LAB_%=;\n\t"
        "}\n"
        :: "r"(mbar), "r"(parity) : "memory");
}

// ---------------------------------------------------------------------------
__global__ void __launch_bounds__(THR, 1)
rnn_persistent(const float* __restrict__ Wrec0, const float* __restrict__ Win1,
               const float* __restrict__ Wrec1, const float* __restrict__ b1,
               float* __restrict__ states0, float* __restrict__ states1)
{
    extern __shared__ float sm[];
    float* aS = sm;                  // [2][KC][B], reused as reduce scratch
    float* wS = sm + ABUF;           // [H][NCOLP] k-major, zero-padded

    const unsigned sbase = (unsigned)__cvta_generic_to_shared(sm);
    const unsigned mb0 = sbase + MBAR_OFF;
    const unsigned mb1 = sbase + MBAR_OFF + 8;
    const unsigned abuf0 = sbase;
    const unsigned abuf1 = sbase + CBYTES;

    const int tid  = threadIdx.x;
    const int role = (int)blockIdx.x / NBR;
    const int j    = (int)blockIdx.x - role * NBR;
    const int n0   = (j * H) / NBR;
    const int n1   = ((j + 1) * H) / NBR;
    const int ncol = n1 - n0;            // 20 or 21

    // split-K slice / microtile mapping
    const int kt     = tid >> 6;         // k-slice 0..7
    const int tl     = tid & 63;
    const int bgroup = tl & 7;           // 8 batches -> bbase = bgroup*8
    const int cgroup = tl >> 3;          // 3 cols    -> cbase = cgroup*3
    const int bbase  = bgroup * 8;
    const int cbase  = cgroup * 3;

    // One-time weight load: wS[k][n] = W[n0+n][k], zero for n >= ncol
    const float* Wsrc = role == 0 ? Wrec0 : (role == 1 ? Win1 : Wrec1);
    for (int it = tid; it < NCOLP * (H / 4); it += THR) {
        int n  = it % NCOLP;
        int k4 = (it / NCOLP) * 4;
        float4 w = make_float4(0.f, 0.f, 0.f, 0.f);
        if (n < ncol) w = *(const float4*)(Wsrc + (size_t)(n0 + n) * H + k4);
        wS[(k4 + 0) * NCOLP + n] = w.x; wS[(k4 + 1) * NCOLP + n] = w.y;
        wS[(k4 + 2) * NCOLP + n] = w.z; wS[(k4 + 3) * NCOLP + n] = w.w;
    }
    // epilogue mapping: 4 contiguous batches of one col per thread
    const int en = tid >> 4;             // local col 0..31 (active if < ncol)
    const int eb = (tid & 15) * 4;       // batch base 0..60
    const bool ecol = (en < ncol);
    const float b1v = (role == 1 && ecol) ? b1[n0 + en] : 0.f;

    if (tid == 0) { mbar_init(mb0, 1); mbar_init(mb1, 1); }
    asm volatile("fence.proxy.async.shared::cta;" ::: "memory");
    __syncthreads();

    unsigned par0 = 0, par1 = 0;
    float v[4] = {0.f, 0.f, 0.f, 0.f};

    for (int p = 0; p < T + 2; p++) {
        int t; const float* asrc = nullptr; bool act, dogemm;
        if (role == 0) {
            t = p; act = (t < T); dogemm = act && (p > 0);
            if (dogemm) asrc = g_s0f + (size_t)(p - 1) * HB;
        } else if (role == 1) {
            t = p - 1; act = (t >= 0 && t < T); dogemm = act;
            if (dogemm) asrc = g_s0f + (size_t)t * HB;
        } else {
            t = p - 2; act = (t >= 0 && t < T); dogemm = act && (t > 0);
            if (dogemm) asrc = g_s1f + (size_t)(t - 1) * HB;
        }

        // acc[col 0..2][batch-pair 0..3]
        unsigned long long acc[3][4];
        #pragma unroll
        for (int c2 = 0; c2 < 3; c2++)
            #pragma unroll
            for (int q = 0; q < 4; q++) acc[c2][q] = 0ull;

        if (dogemm) {
            if (tid == 0) {                       // prefetch chunk 0
                mbar_expect_tx(mb0, CBYTES);
                bulk_g2s(abuf0, asrc, CBYTES, mb0);
            }
            for (int c = 0; c < NCH; c++) {
                if (c + 1 < NCH && tid == 0) {    // prefetch chunk c+1
                    unsigned dst = ((c + 1) & 1) ? abuf1 : abuf0;
                    unsigned mbn = ((c + 1) & 1) ? mb1 : mb0;
                    mbar_expect_tx(mbn, CBYTES);
                    bulk_g2s(dst, asrc + (size_t)(c + 1) * KC * B, CBYTES, mbn);
                }
                if (c & 1) { mbar_wait(mb1, par1); par1 ^= 1; }
                else       { mbar_wait(mb0, par0); par0 ^= 1; }

                const float* ab = aS + (c & 1) * (KC * B) + (kt * 16) * B + bbase;
                const float* wb = wS + (c * KC + kt * 16) * NCOLP + cbase;
                #pragma unroll
                for (int kk = 0; kk < 16; kk++) {
                    ulonglong2 A0 = *(const ulonglong2*)(ab + kk * B);      // b..b+3
                    ulonglong2 A1 = *(const ulonglong2*)(ab + kk * B + 4);  // b+4..b+7
                    unsigned long long w0 = dup2(wb[kk * NCOLP + 0]);
                    unsigned long long w1 = dup2(wb[kk * NCOLP + 1]);
                    unsigned long long w2 = dup2(wb[kk * NCOLP + 2]);
                    // ordered so consecutive FFMA2 share the A operand (.reuse)
                    fma2(acc[0][0], A0.x, w0); fma2(acc[1][0], A0.x, w1);
                    fma2(acc[2][0], A0.x, w2);
                    fma2(acc[0][1], A0.y, w0); fma2(acc[1][1], A0.y, w1);
                    fma2(acc[2][1], A0.y, w2);
                    fma2(acc[0][2], A1.x, w0); fma2(acc[1][2], A1.x, w1);
                    fma2(acc[2][2], A1.x, w2);
                    fma2(acc[0][3], A1.y, w0); fma2(acc[1][3], A1.y, w1);
                    fma2(acc[2][3], A1.y, w2);
                }
                __syncthreads();   // all reads of this buffer done
            }
        }

        float fr[4];
        bool havefr = false;

        if (act) {
            // split-K partials -> smem: red[n][kt][pair]
            unsigned long long* red = (unsigned long long*)aS;
            #pragma unroll
            for (int c2 = 0; c2 < 3; c2++)
                #pragma unroll
                for (int q = 0; q < 4; q++)
                    red[(cbase + c2) * 256 + kt * 32 + bgroup * 4 + q] = acc[c2][q];
            __syncthreads();

            if (ecol) {
                float4 s = make_float4(0.f, 0.f, 0.f, 0.f);
                #pragma unroll
                for (int q = 0; q < 8; q++) {
                    float4 pz = *(const float4*)&aS[en * 512 + q * 64 + eb];
                    s.x += pz.x; s.y += pz.y; s.z += pz.z; s.w += pz.w;
                }
                const size_t vo = ((size_t)t * H + n0 + en) * B + eb;
                if (role == 1) {
                    float4 o = make_float4(s.x + b1v, s.y + b1v,
                                           s.z + b1v, s.w + b1v);
                    *(float4*)&g_pin[(size_t)(t & 1) * HB +
                                     (size_t)(n0 + en) * B + eb] = o;
                } else {
                    float4 add;
                    if (role == 0)
                        add = *(const float4*)&g_xin0[vo];
                    else
                        add = __ldcg((const float4*)&g_pin[(size_t)(t & 1) * HB +
                                                           (size_t)(n0 + en) * B + eb]);
                    v[0] = OMA * v[0] + AL * (s.x + add.x);
                    v[1] = OMA * v[1] + AL * (s.y + add.y);
                    v[2] = OMA * v[2] + AL * (s.z + add.z);
                    v[3] = OMA * v[3] + AL * (s.w + add.w);
                    fr[0] = fmaxf(v[0], 0.f); fr[1] = fmaxf(v[1], 0.f);
                    fr[2] = fmaxf(v[2], 0.f); fr[3] = fmaxf(v[3], 0.f);
                    havefr = true;
                    float* dst = (role == 0) ? g_s0f : g_s1f;
                    *(float4*)&dst[vo] = make_float4(fr[0], fr[1], fr[2], fr[3]);
                }
            }
        }

        if (p < T + 1) {
            // -- grid barrier, arrival first; strided d_out stores hidden under wait
            __syncthreads();
            unsigned gen;
            if (tid == 0) {
                __threadfence();
                gen = g_gen;
                if (atomicAdd(&g_cnt, 1u) == NBLK - 1) {
                    g_cnt = 0;
                    __threadfence();
                    g_gen = gen + 1;
                }
            }
            if (havefr) {   // d_out states store (not consumed in-kernel)
                float* st = (role == 0) ? states0 : states1;
                #pragma unroll
                for (int bl = 0; bl < 4; bl++)
                    st[((size_t)(eb + bl) * T + t) * H + n0 + en] = fr[bl];
            }
            if (tid == 0) {
                while (g_gen == gen) {}
                __threadfence();
            }
            __syncthreads();
        } else if (havefr) {   // last phase: just store
            float* st = (role == 0) ? states0 : states1;
            #pragma unroll
            for (int bl = 0; bl < 4; bl++)
                st[((size_t)(eb + bl) * T + t) * H + n0 + en] = fr[bl];
        }
    }
}

// ---------------------------------------------------------------------------
// gemm_in0: per timestep t, xin0[t][h][b] = W_in0[h,:] . x[b,t,:] + b0[h]
// ---------------------------------------------------------------------------
__global__ void __launch_bounds__(256)
gemm_in0_kernel(const float* __restrict__ x,
                const float* __restrict__ Win0,
                const float* __restrict__ b0)
{
    __shared__ float aS[16 * 64];
    __shared__ float bS[16 * 64];
    const int tid = threadIdx.x;
    const int m0 = blockIdx.x * 64;
    const int t  = blockIdx.y;
    const int lr = tid >> 2;
    const int lk = (tid & 3) * 4;
    const int tm4 = (tid >> 4) * 4;
    const int tn4 = (tid & 15) * 4;
    float acc[4][4] = {};
    const float* ap = Win0 + (size_t)(m0 + lr) * DIN + lk;
    const float* bp = x + ((size_t)lr * T + t) * DIN + lk;

    for (int k0 = 0; k0 < DIN; k0 += 16) {
        float4 av = *(const float4*)(ap + k0);
        float4 bv = *(const float4*)(bp + k0);
        __syncthreads();
        aS[(lk + 0) * 64 + lr] = av.x; aS[(lk + 1) * 64 + lr] = av.y;
        aS[(lk + 2) * 64 + lr] = av.z; aS[(lk + 3) * 64 + lr] = av.w;
        bS[(lk + 0) * 64 + lr] = bv.x; bS[(lk + 1) * 64 + lr] = bv.y;
        bS[(lk + 2) * 64 + lr] = bv.z; bS[(lk + 3) * 64 + lr] = bv.w;
        __syncthreads();
        #pragma unroll
        for (int kk = 0; kk < 16; kk++) {
            float4 a = *(const float4*)&aS[kk * 64 + tm4];
            float4 b = *(const float4*)&bS[kk * 64 + tn4];
            acc[0][0] += a.x * b.x; acc[0][1] += a.x * b.y;
            acc[0][2] += a.x * b.z; acc[0][3] += a.x * b.w;
            acc[1][0] += a.y * b.x; acc[1][1] += a.y * b.y;
            acc[1][2] += a.y * b.z; acc[1][3] += a.y * b.w;
            acc[2][0] += a.z * b.x; acc[2][1] += a.z * b.y;
            acc[2][2] += a.z * b.z; acc[2][3] += a.z * b.w;
            acc[3][0] += a.w * b.x; acc[3][1] += a.w * b.y;
            acc[3][2] += a.w * b.z; acc[3][3] += a.w * b.w;
        }
    }
    #pragma unroll
    for (int i = 0; i < 4; i++) {
        float bb = b0[m0 + tm4 + i];
        float4 o = make_float4(acc[i][0] + bb, acc[i][1] + bb,
                               acc[i][2] + bb, acc[i][3] + bb);
        *(float4*)&g_xin0[((size_t)t * H + m0 + tm4 + i) * B + tn4] = o;
    }
}

// ---------------------------------------------------------------------------
// gemm_out: output[B*T, DOUT] = states1[B*T, H] @ W_out^T + b_out
// ---------------------------------------------------------------------------
__global__ void __launch_bounds__(256)
gemm_out_kernel(const float* __restrict__ states1,
                const float* __restrict__ Wout,
                const float* __restrict__ bout,
                float* __restrict__ out)
{
    __shared__ float aS[16 * 64];
    __shared__ float bS[16 * 64];
    const int tid = threadIdx.x;
    const int m0 = blockIdx.x * 64;
    const int n0 = blockIdx.y * 64;
    const int lr = tid >> 2;
    const int lk = (tid & 3) * 4;
    const int tm4 = (tid >> 4) * 4;
    const int tn4 = (tid & 15) * 4;
    float acc[4][4] = {};
    const float* ap = states1 + (size_t)(m0 + lr) * H + lk;
    const float* bp = Wout    + (size_t)(n0 + lr) * H + lk;

    for (int k0 = 0; k0 < H; k0 += 16) {
        float4 av = *(const float4*)(ap + k0);
        float4 bv = *(const float4*)(bp + k0);
        __syncthreads();
        aS[(lk + 0) * 64 + lr] = av.x; aS[(lk + 1) * 64 + lr] = av.y;
        aS[(lk + 2) * 64 + lr] = av.z; aS[(lk + 3) * 64 + lr] = av.w;
        bS[(lk + 0) * 64 + lr] = bv.x; bS[(lk + 1) * 64 + lr] = bv.y;
        bS[(lk + 2) * 64 + lr] = bv.z; bS[(lk + 3) * 64 + lr] = bv.w;
        __syncthreads();
        #pragma unroll
        for (int kk = 0; kk < 16; kk++) {
            float4 a = *(const float4*)&aS[kk * 64 + tm4];
            float4 b = *(const float4*)&bS[kk * 64 + tn4];
            acc[0][0] += a.x * b.x; acc[0][1] += a.x * b.y;
            acc[0][2] += a.x * b.z; acc[0][3] += a.x * b.w;
            acc[1][0] += a.y * b.x; acc[1][1] += a.y * b.y;
            acc[1][2] += a.y * b.z; acc[1][3] += a.y * b.w;
            acc[2][0] += a.z * b.x; acc[2][1] += a.z * b.y;
            acc[2][2] += a.z * b.z; acc[2][3] += a.z * b.w;
            acc[3][0] += a.w * b.x; acc[3][1] += a.w * b.y;
            acc[3][2] += a.w * b.z; acc[3][3] += a.w * b.w;
        }
    }
    #pragma unroll
    for (int i = 0; i < 4; i++) {
        float4 bb = *(const float4*)&bout[n0 + tn4];
        int gm = m0 + tm4 + i;
        float4 o = make_float4(acc[i][0] + bb.x, acc[i][1] + bb.y,
                               acc[i][2] + bb.z, acc[i][3] + bb.w);
        *(float4*)&out[(size_t)gm * DOUT + n0 + tn4] = o;
    }
}

// ---------------------------------------------------------------------------
extern "C" void kernel_launch(void* const* d_in, const int* in_sizes, int n_in,
                              void* d_out, int out_size)
{
    (void)in_sizes; (void)n_in; (void)out_size;
    const float* x     = (const float*)d_in[0];
    const float* Win0  = (const float*)d_in[1];
    const float* Wrec0 = (const float*)d_in[2];
    const float* b0    = (const float*)d_in[3];
    const float* Win1  = (const float*)d_in[4];
    const float* Wrec1 = (const float*)d_in[5];
    const float* b1    = (const float*)d_in[6];
    const float* Wout  = (const float*)d_in[7];
    const float* bout  = (const float*)d_in[8];

    float* out     = (float*)d_out;                   // [B][T][DOUT]
    float* states0 = out + (size_t)B * T * DOUT;      // [B][T][H]
    float* states1 = states0 + (size_t)B * T * H;     // [B][T][H]

    cudaFuncSetAttribute(rnn_persistent,
                         cudaFuncAttributeMaxDynamicSharedMemorySize, SMEM_P);

    gemm_in0_kernel<<<dim3(H / 64, T), 256>>>(x, Win0, b0);
    rnn_persistent<<<NBLK, THR, SMEM_P>>>(Wrec0, Win1, Wrec1, b1,
                                          states0, states1);
    gemm_out_kernel<<<dim3((B * T) / 64, DOUT / 64), 256>>>(states1, Wout,
                                                            bout, out);
}

// round 12
// speedup vs baseline: 1.7244x; 1.7236x over previous
#include <cuda_runtime.h>
#include <cuda_bf16.h>
#include <cstdint>

// ---------------------------------------------------------------------------
// Leaky CTRNN scan on HMMA (mma.sync m16n8k16 bf16, 3-term split).
// B=64 T=512 H=1024.  96 persistent blocks x 128 thr, 513 phases:
//   role0 (blk  0-31): fr0(p)   = relu(v0=.9v0+.1(Wrec0@fr0(p-1) + xin0)), K=1024
//   role1 (blk 32-95): fr1(p-1) = relu(v1=.9v1+.1([Wrec1|Win1]@[fr1(p-2);fr0(p-1)] + b1)), K=2048
// Weights persist in smem as bf16 hi/lo (swizzled for ldmatrix); fr streams
// from GMEM bf16 hi/lo chunk images via cp.async.bulk, double-buffered.
// ---------------------------------------------------------------------------

namespace {
constexpr int B = 64, T = 512, DIN = 256, H = 1024, DOUT = 256;
constexpr float AL = 0.1f, OMA = 0.9f;
constexpr int NBLK = 96, THR = 128;
constexpr int CHB = 32768;               // fr chunk bytes: [2][64][256]
constexpr int SM_W  = 0;                 // weights: 131072 bytes
constexpr int SM_ST = 131072;            // staging: 2 x CHB
constexpr int SM_MB = SM_ST + 2 * CHB;   // 196608: two mbarriers
constexpr int SMEM_T = SM_MB + 64;
}

// GMEM scratch (allocation-free rule)
__device__ float g_xin0[(size_t)T * H * B];                  // [t][h][b]
__device__ __align__(128) unsigned char g_f0img[513][8][CHB]; // slot t+1
__device__ __align__(128) unsigned char g_f1img[513][8][CHB];
__device__ volatile unsigned g_gen;
__device__ unsigned g_cnt;

// ---- PTX helpers ------------------------------------------------------------
__device__ __forceinline__ void mbar_init(unsigned m, unsigned c) {
    asm volatile("mbarrier.init.shared.b64 [%0], %1;" :: "r"(m), "r"(c) : "memory");
}
__device__ __forceinline__ void mbar_tx(unsigned m, unsigned b) {
    asm volatile("mbarrier.arrive.expect_tx.shared.b64 _, [%0], %1;" :: "r"(m), "r"(b) : "memory");
}
__device__ __forceinline__ void bulk(unsigned d, const void* s, unsigned b, unsigned m) {
    asm volatile("cp.async.bulk.shared::cta.global.mbarrier::complete_tx::bytes [%0], [%1], %2, [%3];"
                 :: "r"(d), "l"(s), "r"(b), "r"(m) : "memory");
}
__device__ __forceinline__ void mwait(unsigned m, unsigned p) {
    asm volatile("{\n\t.reg .pred P;\nL_%=:\n\tmbarrier.try_wait.parity.shared.b64 P, [%0], %1;\n\t@!P bra L_%=;\n\t}"
                 :: "r"(m), "r"(p) : "memory");
}
__device__ __forceinline__ void ldsm4(uint32_t* r, unsigned a) {
    asm volatile("ldmatrix.sync.aligned.m8n8.x4.shared.b16 {%0,%1,%2,%3}, [%4];"
                 : "=r"(r[0]), "=r"(r[1]), "=r"(r[2]), "=r"(r[3]) : "r"(a));
}
__device__ __forceinline__ void mma16816(float* d, const uint32_t* a, const uint32_t* b) {
    asm volatile("mma.sync.aligned.m16n8k16.row.col.f32.bf16.bf16.f32 "
                 "{%0,%1,%2,%3},{%4,%5,%6,%7},{%8,%9},{%0,%1,%2,%3};"
                 : "+f"(d[0]), "+f"(d[1]), "+f"(d[2]), "+f"(d[3])
                 : "r"(a[0]), "r"(a[1]), "r"(a[2]), "r"(a[3]), "r"(b[0]), "r"(b[1]));
}
__device__ __forceinline__ void gridbar() {
    __syncthreads();
    if (threadIdx.x == 0) {
        __threadfence();
        unsigned g = g_gen;
        if (atomicAdd(&g_cnt, 1u) == NBLK - 1) { g_cnt = 0; __threadfence(); g_gen = g + 1; }
        else { while (g_gen == g) {} __threadfence(); }
    }
    __syncthreads();
}

__global__ void prep_zero() {
    const size_t n = 8ull * CHB / 16;     // one t-slot per image
    float4 z = make_float4(0.f, 0.f, 0.f, 0.f);
    for (size_t i = blockIdx.x * blockDim.x + threadIdx.x; i < n;
         i += (size_t)gridDim.x * blockDim.x) {
        ((float4*)&g_f0img[0][0][0])[i] = z;
        ((float4*)&g_f1img[0][0][0])[i] = z;
    }
}

// ---------------------------------------------------------------------------
__global__ void __launch_bounds__(THR, 1)
rnn_mma(const float* __restrict__ Wrec0, const float* __restrict__ Wrec1,
        const float* __restrict__ Win1, const float* __restrict__ b1,
        float* __restrict__ st0, float* __restrict__ st1)
{
    extern __shared__ unsigned char smc[];
    const unsigned sb = (unsigned)__cvta_generic_to_shared(smc);
    const int tid = threadIdx.x, wid = tid >> 5, lane = tid & 31, bid = blockIdx.x;
    const bool r0 = (bid < 32);
    const int HR = r0 ? 32 : 16;          // weight rows in smem tile
    const int PW = HR * 256;              // weight plane bytes
    const int CW = 2 * PW;                // weight chunk bytes
    const int NC = r0 ? 8 : 16;           // k-chunks per phase
    const int h0blk = r0 ? bid * 32 : (bid - 32) * 16;
    const int h0w = r0 ? (wid >> 1) * 16 : 0;      // warp m base (block-local)
    const int bn  = r0 ? (wid & 1) * 32 : wid * 16; // warp n base
    const int NT  = r0 ? 4 : 2;           // n8 tiles per warp
    const int NBF = NT >> 1;              // B ldmatrix.x4 per plane

    // --- one-time: weights -> smem bf16 hi/lo, ldmatrix-swizzled ---
    {
        const int KT = r0 ? 1024 : 2048;
        for (int i = tid; i < HR * KT; i += THR) {
            int hl = i / KT, k = i - hl * KT;
            float val;
            if (r0) val = Wrec0[(size_t)(h0blk + hl) * H + k];
            else    val = (k < H) ? Wrec1[(size_t)(h0blk + hl) * H + k]
                                  : Win1[(size_t)(h0blk + hl) * H + (k - H)];
            __nv_bfloat16 hi = __float2bfloat16(val);
            __nv_bfloat16 lo = __float2bfloat16(val - __bfloat162float(hi));
            int c = k >> 7, kl = k & 127, u = kl >> 3;
            unsigned off = SM_W + (unsigned)c * CW + (unsigned)hl * 256
                         + ((unsigned)(u ^ (hl & 7)) << 4) + (kl & 7) * 2;
            *(__nv_bfloat16*)(smc + off) = hi;
            *(__nv_bfloat16*)(smc + off + PW) = lo;
        }
    }
    if (tid == 0) { mbar_init(sb + SM_MB, 1); mbar_init(sb + SM_MB + 8, 1); }
    asm volatile("fence.proxy.async.shared::cta;" ::: "memory");
    __syncthreads();

    // fragment address precompute
    const int ar  = h0w + (lane & 7) + ((lane >> 3) & 1) * 8;  // A row
    const int akh = (lane >> 4) & 1;
    const int ar7 = ar & 7;
    int brr[2], br7[2];
    #pragma unroll
    for (int f = 0; f < 2; f++) {
        brr[f] = bn + f * 16 + (lane & 7) + ((lane >> 4) & 1) * 8;
        br7[f] = brr[f] & 7;
    }
    const int bkh = (lane >> 3) & 1;

    float b1a = 0.f, b1b = 0.f;
    if (!r0) { b1a = b1[h0blk + (lane >> 2)]; b1b = b1[h0blk + (lane >> 2) + 8]; }

    unsigned par[2] = {0, 0};
    const unsigned mb[2]  = {sb + SM_MB, sb + SM_MB + 8};
    const unsigned stg[2] = {sb + SM_ST, sb + SM_ST + CHB};

    float v[4][4];
    #pragma unroll
    for (int i = 0; i < 4; i++)
        #pragma unroll
        for (int j = 0; j < 4; j++) v[i][j] = 0.f;

    for (int p = 0; p <= T; p++) {
        const int t = r0 ? p : (p - 1);
        const bool act = r0 ? (p < T) : (p >= 1);
        if (act) {
            auto src = [&](int c) -> const void* {
                if (r0) return (const void*)g_f0img[p][c];        // fr0(p-1)
                return (c < 8) ? (const void*)g_f1img[t][c]        // fr1(t-1)
                               : (const void*)g_f0img[p][c - 8];   // fr0(p-1)
            };
            if (tid == 0) {
                #pragma unroll
                for (int c = 0; c < 2; c++) {
                    mbar_tx(mb[c], CHB);
                    bulk(stg[c], src(c), CHB, mb[c]);
                }
            }
            float d[4][4];
            #pragma unroll
            for (int i = 0; i < 4; i++)
                #pragma unroll
                for (int j = 0; j < 4; j++) d[i][j] = 0.f;

            for (int c = 0; c < NC; c++) {
                const int bf = c & 1;
                mwait(mb[bf], par[bf]); par[bf] ^= 1;
                const unsigned wb = sb + SM_W + (unsigned)c * CW;
                const unsigned sg = stg[bf];
                #pragma unroll
                for (int ks = 0; ks < 8; ks++) {
                    uint32_t ahi[4], alo[4], bh[2][4], bl[2][4];
                    unsigned ua = ((unsigned)((ks * 2 + akh) ^ ar7)) << 4;
                    ldsm4(ahi, wb + (unsigned)ar * 256 + ua);
                    ldsm4(alo, wb + PW + (unsigned)ar * 256 + ua);
                    #pragma unroll
                    for (int f = 0; f < 2; f++) {
                        if (f >= NBF) break;
                        unsigned ub = ((unsigned)((ks * 2 + bkh) ^ br7[f])) << 4;
                        unsigned ba = sg + (unsigned)brr[f] * 256 + ub;
                        ldsm4(bh[f], ba);
                        ldsm4(bl[f], ba + 16384);
                    }
                    #pragma unroll
                    for (int nt = 0; nt < 4; nt++) {
                        if (nt >= NT) break;
                        const uint32_t* BH = &bh[nt >> 1][(nt & 1) * 2];
                        const uint32_t* BL = &bl[nt >> 1][(nt & 1) * 2];
                        mma16816(d[nt], ahi, BH);
                        mma16816(d[nt], ahi, BL);
                        mma16816(d[nt], alo, BH);
                    }
                }
                __syncthreads();
                if (tid == 0 && c + 2 < NC) {
                    mbar_tx(mb[bf], CHB);
                    bulk(stg[bf], src(c + 2), CHB, mb[bf]);
                }
            }

            // ---- epilogue: leaky update, stage tiles, coalesced writes ----
            const int Wd = r0 ? 32 : 16;
            float* epf = (float*)(smc + SM_ST);
            __nv_bfloat16* ehi = (__nv_bfloat16*)(smc + SM_ST + 64 * Wd * 4);
            __nv_bfloat16* elo = ehi + 64 * Wd;
            #pragma unroll
            for (int nt = 0; nt < 4; nt++) {
                if (nt >= NT) break;
                #pragma unroll
                for (int j = 0; j < 4; j++) {
                    int hl = h0w + (lane >> 2) + (j >> 1) * 8;
                    int bb = bn + nt * 8 + (lane & 3) * 2 + (j & 1);
                    float add;
                    if (r0) add = g_xin0[((size_t)t * H + h0blk + hl) * B + bb];
                    else    add = (j >> 1) ? b1b : b1a;
                    float nv = OMA * v[nt][j] + AL * (d[nt][j] + add);
                    v[nt][j] = nv;
                    float fr = fmaxf(nv, 0.f);
                    epf[bb * Wd + hl] = fr;
                    __nv_bfloat16 hi = __float2bfloat16(fr);
                    ehi[bb * Wd + hl] = hi;
                    elo[bb * Wd + hl] = __float2bfloat16(fr - __bfloat162float(hi));
                }
            }
            __syncthreads();
            {
                const int bb = tid >> 1, half = tid & 1;
                float* st = r0 ? st0 : st1;
                const float* srow = epf + bb * Wd + half * (Wd / 2);
                float* drow = st + ((size_t)bb * T + t) * H + h0blk + half * (Wd / 2);
                #pragma unroll
                for (int q = 0; q < 4; q++) {
                    if (q >= Wd / 8) break;
                    ((float4*)drow)[q] = ((const float4*)srow)[q];
                }
                unsigned char* img = r0 ? g_f0img[p + 1][h0blk >> 7]
                                        : g_f1img[t + 1][h0blk >> 7];
                const int ub0 = (h0blk & 127) >> 3;
                const int upt = (Wd >> 3) >> 1;        // units per thread
                #pragma unroll
                for (int uu = 0; uu < 2; uu++) {
                    if (uu >= upt) break;
                    int ul = half * upt + uu;
                    int ug = ub0 + ul;
                    unsigned dsto = (unsigned)bb * 256 + ((unsigned)(ug ^ (bb & 7)) << 4);
                    uint4 hv = *(const uint4*)((const unsigned char*)ehi + bb * Wd * 2 + ul * 16);
                    uint4 lv = *(const uint4*)((const unsigned char*)elo + bb * Wd * 2 + ul * 16);
                    *(uint4*)(img + dsto) = hv;
                    *(uint4*)(img + 16384 + dsto) = lv;
                }
            }
            __syncthreads();
        }
        if (p < T) gridbar();
    }
}

// ---------------------------------------------------------------------------
// fp32 tiled GEMM: mode0 = xin0 (A=Win0, B=x per-t -> g_xin0), mode1 = output
// ---------------------------------------------------------------------------
__global__ void __launch_bounds__(256)
gemm_fp32(int mode, const float* __restrict__ A, const float* __restrict__ Bm,
          const float* __restrict__ bias, float* __restrict__ C)
{
    __shared__ float aS[16 * 64], bS[16 * 64];
    const int tid = threadIdx.x, m0 = blockIdx.x * 64;
    const int t = blockIdx.y, n0 = mode ? blockIdx.z * 64 : 0;
    const int lr = tid >> 2, lk = (tid & 3) * 4;
    const int tm4 = (tid >> 4) * 4, tn4 = (tid & 15) * 4;
    const int K = mode ? H : DIN;
    float acc[4][4] = {};
    const float* ap; const float* bp;
    if (mode) { ap = A + (size_t)(m0 + lr) * H + lk; bp = Bm + (size_t)(n0 + lr) * H + lk; }
    else      { ap = A + (size_t)(m0 + lr) * DIN + lk; bp = Bm + ((size_t)lr * T + t) * DIN + lk; }

    for (int k0 = 0; k0 < K; k0 += 16) {
        float4 av = *(const float4*)(ap + k0);
        float4 bv = *(const float4*)(bp + k0);
        __syncthreads();
        aS[(lk+0)*64+lr]=av.x; aS[(lk+1)*64+lr]=av.y; aS[(lk+2)*64+lr]=av.z; aS[(lk+3)*64+lr]=av.w;
        bS[(lk+0)*64+lr]=bv.x; bS[(lk+1)*64+lr]=bv.y; bS[(lk+2)*64+lr]=bv.z; bS[(lk+3)*64+lr]=bv.w;
        __syncthreads();
        #pragma unroll
        for (int kk = 0; kk < 16; kk++) {
            float4 a = *(const float4*)&aS[kk*64+tm4];
            float4 b = *(const float4*)&bS[kk*64+tn4];
            acc[0][0]+=a.x*b.x; acc[0][1]+=a.x*b.y; acc[0][2]+=a.x*b.z; acc[0][3]+=a.x*b.w;
            acc[1][0]+=a.y*b.x; acc[1][1]+=a.y*b.y; acc[1][2]+=a.y*b.z; acc[1][3]+=a.y*b.w;
            acc[2][0]+=a.z*b.x; acc[2][1]+=a.z*b.y; acc[2][2]+=a.z*b.z; acc[2][3]+=a.z*b.w;
            acc[3][0]+=a.w*b.x; acc[3][1]+=a.w*b.y; acc[3][2]+=a.w*b.z; acc[3][3]+=a.w*b.w;
        }
    }
    if (mode) {
        float4 bb = *(const float4*)&bias[n0 + tn4];
        #pragma unroll
        for (int i = 0; i < 4; i++) {
            int gm = m0 + tm4 + i;
            float4 o = make_float4(acc[i][0]+bb.x, acc[i][1]+bb.y, acc[i][2]+bb.z, acc[i][3]+bb.w);
            *(float4*)&C[(size_t)gm * DOUT + n0 + tn4] = o;
        }
    } else {
        #pragma unroll
        for (int i = 0; i < 4; i++) {
            float bb = bias[m0 + tm4 + i];
            float4 o = make_float4(acc[i][0]+bb, acc[i][1]+bb, acc[i][2]+bb, acc[i][3]+bb);
            *(float4*)&g_xin0[((size_t)t * H + m0 + tm4 + i) * B + tn4] = o;
        }
    }
}

// ---------------------------------------------------------------------------
extern "C" void kernel_launch(void* const* d_in, const int* in_sizes, int n_in,
                              void* d_out, int out_size)
{
    (void)in_sizes; (void)n_in; (void)out_size;
    const float* x     = (const float*)d_in[0];
    const float* Win0  = (const float*)d_in[1];
    const float* Wrec0 = (const float*)d_in[2];
    const float* b0    = (const float*)d_in[3];
    const float* Win1  = (const float*)d_in[4];
    const float* Wrec1 = (const float*)d_in[5];
    const float* b1    = (const float*)d_in[6];
    const float* Wout  = (const float*)d_in[7];
    const float* bout  = (const float*)d_in[8];

    float* out = (float*)d_out;
    float* states0 = out + (size_t)B * T * DOUT;
    float* states1 = states0 + (size_t)B * T * H;

    cudaFuncSetAttribute(rnn_mma, cudaFuncAttributeMaxDynamicSharedMemorySize, SMEM_T);

    prep_zero<<<128, 256>>>();
    gemm_fp32<<<dim3(H / 64, T, 1), 256>>>(0, Win0, x, b0, nullptr);
    rnn_mma<<<NBLK, THR, SMEM_T>>>(Wrec0, Wrec1, Win1, b1, states0, states1);
    gemm_fp32<<<dim3((B * T) / 64, 1, DOUT / 64), 256>>>(1, states1, Wout, bout, out);
}